// round 1
// baseline (speedup 1.0000x reference)
#include <cuda_runtime.h>

#define N_NODES 100000
#define E_MAX   1000000

// ---------------- device scratch (no allocs allowed) ----------------
__device__ int   g_deg[N_NODES];
__device__ int   g_rowptr[N_NODES];
__device__ int   g_cursor[N_NODES];
__device__ int   g_adj[E_MAX];
__device__ float g_h[N_NODES * 64];
__device__ int   g_is64;

// ---------------- edge dtype detection (int64 vs int32) ----------------
// If edge_index is int64, every odd 32-bit word (high half of values < 1e5)
// is zero. If int32, odd words are random node ids — OR over 4096 samples.
__global__ void k_detect(const unsigned int* __restrict__ w) {
    __shared__ unsigned int s;
    if (threadIdx.x == 0) s = 0u;
    __syncthreads();
    unsigned int acc = 0u;
    for (int i = threadIdx.x; i < 4096; i += 256) acc |= w[2 * i + 1];
    atomicOr(&s, acc);
    __syncthreads();
    if (threadIdx.x == 0) g_is64 = (s == 0u) ? 1 : 0;
}

__device__ __forceinline__ int edge_at(const void* ei, long long i) {
    if (g_is64) return (int)((const long long*)ei)[i];
    return ((const int*)ei)[i];
}

// ---------------- CSR build ----------------
__global__ void k_zerodeg() {
    int i = blockIdx.x * blockDim.x + threadIdx.x;
    if (i < N_NODES) g_deg[i] = 0;
}

__global__ void k_degree(const void* __restrict__ ei, int E) {
    int i = blockIdx.x * blockDim.x + threadIdx.x;
    if (i >= E) return;
    int dst = edge_at(ei, (long long)E + i);
    atomicAdd(&g_deg[dst], 1);
}

// single-block exclusive scan over 100k degrees
__global__ void k_scan() {
    __shared__ int s_sums[1024];
    const int t = threadIdx.x;
    const int chunk = (N_NODES + 1023) / 1024;
    const int s = t * chunk;
    const int e = min(s + chunk, N_NODES);
    int acc = 0;
    for (int i = s; i < e; i++) acc += g_deg[i];
    s_sums[t] = acc;
    __syncthreads();
    for (int off = 1; off < 1024; off <<= 1) {
        int v = (t >= off) ? s_sums[t - off] : 0;
        __syncthreads();
        s_sums[t] += v;
        __syncthreads();
    }
    int run = (t > 0) ? s_sums[t - 1] : 0;
    for (int i = s; i < e; i++) {
        g_rowptr[i] = run;
        g_cursor[i] = run;
        run += g_deg[i];
    }
}

__global__ void k_fill(const void* __restrict__ ei, int E) {
    int i = blockIdx.x * blockDim.x + threadIdx.x;
    if (i >= E) return;
    int src = edge_at(ei, i);
    int dst = edge_at(ei, (long long)E + i);
    int pos = atomicAdd(&g_cursor[dst], 1);
    g_adj[pos] = src;
}

// ---------------- fused layer: gather-mean + linear + L2 norm (+ReLU) ----
// One warp owns 4 nodes; thread `lane` owns output features {lane, lane+32}.
// s_W holds [Wl; Wr] stacked (128 x FOUT), s_in holds [mean | x] per node.
template <int FOUT, bool RELU>
__global__ void __launch_bounds__(192)
k_layer(const float* __restrict__ xin,   // [N, 64]
        const float* __restrict__ Wl,    // [64, FOUT]
        const float* __restrict__ Wr,    // [64, FOUT]
        const float* __restrict__ bias,  // [FOUT]
        float* __restrict__ out)         // [N, FOUT]
{
    constexpr int OPT = FOUT / 32;  // outputs per thread (2 or 1)
    __shared__ float s_W[128 * FOUT];
    __shared__ __align__(16) float s_in[6][512];

    const int tid  = threadIdx.x;
    const int lane = tid & 31;
    const int w    = tid >> 5;

    for (int i = tid; i < 64 * FOUT; i += 192) {
        s_W[i]             = Wl[i];
        s_W[64 * FOUT + i] = Wr[i];
    }
    __syncthreads();

    float rb[OPT];
#pragma unroll
    for (int o = 0; o < OPT; o++) rb[o] = bias[lane + 32 * o];

    const int warpGid   = blockIdx.x * 6 + w;
    const int warpTotal = gridDim.x * 6;
    float* si = s_in[w];

    for (int base = warpGid * 4; base < N_NODES; base += warpTotal * 4) {
        // ---- phase 1: gather-mean for 4 nodes into shared ----
#pragma unroll
        for (int n = 0; n < 4; n++) {
            const int node  = base + n;
            const int deg   = g_deg[node];
            const int start = g_rowptr[node];
            const float inv = 1.0f / (float)max(deg, 1);
            float m0 = 0.f, m1 = 0.f;
            for (int j0 = 0; j0 < deg; j0 += 32) {
                const int rem = deg - j0;
                int src = 0;
                if (lane < rem) src = g_adj[start + j0 + lane];
                const int cnt = min(32, rem);
#pragma unroll 4
                for (int j = 0; j < cnt; j++) {
                    const int sdx = __shfl_sync(0xffffffffu, src, j) * 64;
                    m0 += xin[sdx + lane];
                    m1 += xin[sdx + 32 + lane];
                }
            }
            si[n * 128 + lane]      = m0 * inv;
            si[n * 128 + 32 + lane] = m1 * inv;
            si[n * 128 + 64 + lane] = xin[node * 64 + lane];
            si[n * 128 + 96 + lane] = xin[node * 64 + 32 + lane];
        }
        __syncwarp();

        // ---- phase 2: [mean|x] @ [Wl;Wr] with 4-node weight reuse ----
        float acc[4][OPT];
#pragma unroll
        for (int n = 0; n < 4; n++)
#pragma unroll
            for (int o = 0; o < OPT; o++) acc[n][o] = rb[o];

        const float4* si4 = (const float4*)si;
#pragma unroll 4
        for (int k4 = 0; k4 < 32; k4++) {
            float4 a0 = si4[k4];
            float4 a1 = si4[32 + k4];
            float4 a2 = si4[64 + k4];
            float4 a3 = si4[96 + k4];
#pragma unroll
            for (int kk = 0; kk < 4; kk++) {
                const int k = k4 * 4 + kk;
#pragma unroll
                for (int o = 0; o < OPT; o++) {
                    const float wv = s_W[k * FOUT + lane + 32 * o];
                    acc[0][o] += ((const float*)&a0)[kk] * wv;
                    acc[1][o] += ((const float*)&a1)[kk] * wv;
                    acc[2][o] += ((const float*)&a2)[kk] * wv;
                    acc[3][o] += ((const float*)&a3)[kk] * wv;
                }
            }
        }
        __syncwarp();

        // ---- phase 3: row L2-normalize (+ReLU) and store ----
#pragma unroll
        for (int n = 0; n < 4; n++) {
            float ss = 0.f;
#pragma unroll
            for (int o = 0; o < OPT; o++) ss += acc[n][o] * acc[n][o];
#pragma unroll
            for (int off = 16; off > 0; off >>= 1)
                ss += __shfl_xor_sync(0xffffffffu, ss, off);
            const float scale = 1.0f / fmaxf(sqrtf(ss), 1e-12f);
#pragma unroll
            for (int o = 0; o < OPT; o++) {
                float v = acc[n][o] * scale;
                if (RELU) v = fmaxf(v, 0.f);
                out[(base + n) * FOUT + lane + 32 * o] = v;
            }
        }
        __syncwarp();
    }
}

// ---------------- launch ----------------
extern "C" void kernel_launch(void* const* d_in, const int* in_sizes, int n_in,
                              void* d_out, int out_size) {
    (void)n_in; (void)out_size;
    const float* x   = (const float*)d_in[0];
    const void*  ei  = d_in[1];
    const float* W1l = (const float*)d_in[2];
    const float* b1  = (const float*)d_in[3];
    const float* W1r = (const float*)d_in[4];
    const float* W2l = (const float*)d_in[5];
    const float* b2  = (const float*)d_in[6];
    const float* W2r = (const float*)d_in[7];
    float* out = (float*)d_out;
    const int E = in_sizes[1] / 2;

    float* hptr = nullptr;
    cudaGetSymbolAddress((void**)&hptr, g_h);

    k_detect<<<1, 256>>>((const unsigned int*)ei);
    k_zerodeg<<<(N_NODES + 255) / 256, 256>>>();
    k_degree<<<(E + 255) / 256, 256>>>(ei, E);
    k_scan<<<1, 1024>>>();
    k_fill<<<(E + 255) / 256, 256>>>(ei, E);

    k_layer<64, true ><<<740, 192>>>(x,    W1l, W1r, b1, hptr);
    k_layer<32, false><<<740, 192>>>(hptr, W2l, W2r, b2, out);
}

// round 2
// speedup vs baseline: 1.7474x; 1.7474x over previous
#include <cuda_runtime.h>

#define N_NODES 100000
#define E_MAX   1000000
#define SCAN_B  1024
#define NSCANB  ((N_NODES + SCAN_B - 1) / SCAN_B)   // 98

// ---------------- device scratch (no allocs allowed) ----------------
__device__ int   g_deg[N_NODES];
__device__ int   g_rowptr[N_NODES];
__device__ int   g_cursor[N_NODES];
__device__ int   g_adj[E_MAX];
__device__ float g_h[N_NODES * 64];
__device__ int   g_blocksum[NSCANB];
__device__ int   g_blockoff[NSCANB];
__device__ int   g_is64;

// ---------------- edge dtype detection (int64 vs int32) ----------------
__global__ void k_detect(const unsigned int* __restrict__ w) {
    __shared__ unsigned int s;
    if (threadIdx.x == 0) s = 0u;
    __syncthreads();
    unsigned int acc = 0u;
    for (int i = threadIdx.x; i < 4096; i += 256) acc |= w[2 * i + 1];
    atomicOr(&s, acc);
    __syncthreads();
    if (threadIdx.x == 0) g_is64 = (s == 0u) ? 1 : 0;
}

__device__ __forceinline__ int edge_at(const void* ei, long long i) {
    if (g_is64) return (int)((const long long*)ei)[i];
    return ((const int*)ei)[i];
}

// ---------------- CSR build ----------------
__global__ void k_zerodeg() {
    int i = blockIdx.x * blockDim.x + threadIdx.x;
    if (i < N_NODES) g_deg[i] = 0;
}

__global__ void k_degree(const void* __restrict__ ei, int E) {
    int i = blockIdx.x * blockDim.x + threadIdx.x;
    if (i >= E) return;
    int dst = edge_at(ei, (long long)E + i);
    atomicAdd(&g_deg[dst], 1);
}

// phase 1: per-block sum of 1024 degrees
__global__ void __launch_bounds__(SCAN_B) k_partial() {
    __shared__ int s_w[32];
    const int i = blockIdx.x * SCAN_B + threadIdx.x;
    int v = (i < N_NODES) ? g_deg[i] : 0;
#pragma unroll
    for (int off = 16; off > 0; off >>= 1)
        v += __shfl_xor_sync(0xffffffffu, v, off);
    if ((threadIdx.x & 31) == 0) s_w[threadIdx.x >> 5] = v;
    __syncthreads();
    if (threadIdx.x < 32) {
        int t = s_w[threadIdx.x];
#pragma unroll
        for (int off = 16; off > 0; off >>= 1)
            t += __shfl_xor_sync(0xffffffffu, t, off);
        if (threadIdx.x == 0) g_blocksum[blockIdx.x] = t;
    }
}

// phase 2: exclusive scan of 98 block sums (tiny, in shared)
__global__ void k_scan_blocks() {
    __shared__ int s[NSCANB];
    if (threadIdx.x < NSCANB) s[threadIdx.x] = g_blocksum[threadIdx.x];
    __syncthreads();
    if (threadIdx.x == 0) {
        int run = 0;
        for (int b = 0; b < NSCANB; b++) { int t = s[b]; s[b] = run; run += t; }
    }
    __syncthreads();
    if (threadIdx.x < NSCANB) g_blockoff[threadIdx.x] = s[threadIdx.x];
}

// phase 3: in-block inclusive scan -> exclusive + block offset
__global__ void __launch_bounds__(SCAN_B) k_write() {
    __shared__ int s[SCAN_B];
    const int t = threadIdx.x;
    const int i = blockIdx.x * SCAN_B + t;
    const int d = (i < N_NODES) ? g_deg[i] : 0;
    s[t] = d;
    __syncthreads();
#pragma unroll
    for (int off = 1; off < SCAN_B; off <<= 1) {
        int v = (t >= off) ? s[t - off] : 0;
        __syncthreads();
        s[t] += v;
        __syncthreads();
    }
    if (i < N_NODES) {
        const int r = g_blockoff[blockIdx.x] + s[t] - d;  // exclusive
        g_rowptr[i] = r;
        g_cursor[i] = r;
    }
}

__global__ void k_fill(const void* __restrict__ ei, int E) {
    int i = blockIdx.x * blockDim.x + threadIdx.x;
    if (i >= E) return;
    int src = edge_at(ei, i);
    int dst = edge_at(ei, (long long)E + i);
    int pos = atomicAdd(&g_cursor[dst], 1);
    g_adj[pos] = src;
}

// ---------------- fused layer: gather-mean + linear + L2 norm (+ReLU) ----
template <int FOUT, bool RELU>
__global__ void __launch_bounds__(192)
k_layer(const float* __restrict__ xin,   // [N, 64]
        const float* __restrict__ Wl,    // [64, FOUT]
        const float* __restrict__ Wr,    // [64, FOUT]
        const float* __restrict__ bias,  // [FOUT]
        float* __restrict__ out)         // [N, FOUT]
{
    constexpr int OPT = FOUT / 32;  // outputs per thread (2 or 1)
    __shared__ float s_W[128 * FOUT];
    __shared__ __align__(16) float s_in[6][512];

    const int tid  = threadIdx.x;
    const int lane = tid & 31;
    const int w    = tid >> 5;

    for (int i = tid; i < 64 * FOUT; i += 192) {
        s_W[i]             = Wl[i];
        s_W[64 * FOUT + i] = Wr[i];
    }
    __syncthreads();

    float rb[OPT];
#pragma unroll
    for (int o = 0; o < OPT; o++) rb[o] = bias[lane + 32 * o];

    const int warpGid   = blockIdx.x * 6 + w;
    const int warpTotal = gridDim.x * 6;
    float* si = s_in[w];

    for (int base = warpGid * 4; base < N_NODES; base += warpTotal * 4) {
        // ---- phase 1: gather-mean for 4 nodes into shared ----
#pragma unroll
        for (int n = 0; n < 4; n++) {
            const int node  = base + n;
            const int deg   = g_deg[node];
            const int start = g_rowptr[node];
            const float inv = 1.0f / (float)max(deg, 1);
            float m0 = 0.f, m1 = 0.f;
            for (int j0 = 0; j0 < deg; j0 += 32) {
                const int rem = deg - j0;
                int src = 0;
                if (lane < rem) src = g_adj[start + j0 + lane];
                const int cnt = min(32, rem);
#pragma unroll 4
                for (int j = 0; j < cnt; j++) {
                    const int sdx = __shfl_sync(0xffffffffu, src, j) * 64;
                    m0 += xin[sdx + lane];
                    m1 += xin[sdx + 32 + lane];
                }
            }
            si[n * 128 + lane]      = m0 * inv;
            si[n * 128 + 32 + lane] = m1 * inv;
            si[n * 128 + 64 + lane] = xin[node * 64 + lane];
            si[n * 128 + 96 + lane] = xin[node * 64 + 32 + lane];
        }
        __syncwarp();

        // ---- phase 2: [mean|x] @ [Wl;Wr] with 4-node weight reuse ----
        float acc[4][OPT];
#pragma unroll
        for (int n = 0; n < 4; n++)
#pragma unroll
            for (int o = 0; o < OPT; o++) acc[n][o] = rb[o];

        const float4* si4 = (const float4*)si;
#pragma unroll 4
        for (int k4 = 0; k4 < 32; k4++) {
            float4 a0 = si4[k4];
            float4 a1 = si4[32 + k4];
            float4 a2 = si4[64 + k4];
            float4 a3 = si4[96 + k4];
#pragma unroll
            for (int kk = 0; kk < 4; kk++) {
                const int k = k4 * 4 + kk;
#pragma unroll
                for (int o = 0; o < OPT; o++) {
                    const float wv = s_W[k * FOUT + lane + 32 * o];
                    acc[0][o] += ((const float*)&a0)[kk] * wv;
                    acc[1][o] += ((const float*)&a1)[kk] * wv;
                    acc[2][o] += ((const float*)&a2)[kk] * wv;
                    acc[3][o] += ((const float*)&a3)[kk] * wv;
                }
            }
        }
        __syncwarp();

        // ---- phase 3: row L2-normalize (+ReLU) and store ----
#pragma unroll
        for (int n = 0; n < 4; n++) {
            float ss = 0.f;
#pragma unroll
            for (int o = 0; o < OPT; o++) ss += acc[n][o] * acc[n][o];
#pragma unroll
            for (int off = 16; off > 0; off >>= 1)
                ss += __shfl_xor_sync(0xffffffffu, ss, off);
            const float scale = 1.0f / fmaxf(sqrtf(ss), 1e-12f);
#pragma unroll
            for (int o = 0; o < OPT; o++) {
                float v = acc[n][o] * scale;
                if (RELU) v = fmaxf(v, 0.f);
                out[(base + n) * FOUT + lane + 32 * o] = v;
            }
        }
        __syncwarp();
    }
}

// ---------------- launch ----------------
extern "C" void kernel_launch(void* const* d_in, const int* in_sizes, int n_in,
                              void* d_out, int out_size) {
    (void)n_in; (void)out_size;
    const float* x   = (const float*)d_in[0];
    const void*  ei  = d_in[1];
    const float* W1l = (const float*)d_in[2];
    const float* b1  = (const float*)d_in[3];
    const float* W1r = (const float*)d_in[4];
    const float* W2l = (const float*)d_in[5];
    const float* b2  = (const float*)d_in[6];
    const float* W2r = (const float*)d_in[7];
    float* out = (float*)d_out;
    const int E = in_sizes[1] / 2;

    float* hptr = nullptr;
    cudaGetSymbolAddress((void**)&hptr, g_h);

    k_detect<<<1, 256>>>((const unsigned int*)ei);
    k_zerodeg<<<(N_NODES + 255) / 256, 256>>>();
    k_degree<<<(E + 255) / 256, 256>>>(ei, E);
    k_partial<<<NSCANB, SCAN_B>>>();
    k_scan_blocks<<<1, 128>>>();
    k_write<<<NSCANB, SCAN_B>>>();
    k_fill<<<(E + 255) / 256, 256>>>(ei, E);

    k_layer<64, true ><<<740, 192>>>(x,    W1l, W1r, b1, hptr);
    k_layer<32, false><<<740, 192>>>(hptr, W2l, W2r, b2, out);
}

// round 4
// speedup vs baseline: 1.9097x; 1.0929x over previous
#include <cuda_runtime.h>

#define N_NODES 100000
#define E_MAX   1000000
#define SCAN_B  1024
#define NSCANB  ((N_NODES + SCAN_B - 1) / SCAN_B)   // 98
#define FULL    0xffffffffu

// ---------------- device scratch (no allocs allowed) ----------------
__device__ int   g_deg[N_NODES];
__device__ int   g_rowptr[N_NODES];
__device__ int   g_cursor[N_NODES];
__device__ int   g_adj[E_MAX];
__device__ float g_h[N_NODES * 64];
__device__ int   g_blocksum[NSCANB];
__device__ int   g_blockoff[NSCANB];
__device__ int   g_is64;

// ---------------- zero degrees + edge dtype detection (merged) ----------
// If edge_index is int64, every odd 32-bit word (values < 1e5) is zero.
__global__ void k_zerodetect(const unsigned int* __restrict__ w) {
    int i = blockIdx.x * blockDim.x + threadIdx.x;
    if (i < N_NODES) g_deg[i] = 0;
    if (blockIdx.x == 0) {
        __shared__ unsigned int s;
        if (threadIdx.x == 0) s = 0u;
        __syncthreads();
        unsigned int acc = 0u;
        for (int k = threadIdx.x; k < 4096; k += blockDim.x) acc |= w[2 * k + 1];
        atomicOr(&s, acc);
        __syncthreads();
        if (threadIdx.x == 0) g_is64 = (s == 0u) ? 1 : 0;
    }
}

__device__ __forceinline__ int edge_at(const void* ei, long long i) {
    if (g_is64) return (int)((const long long*)ei)[i];
    return ((const int*)ei)[i];
}

// ---------------- CSR build ----------------
__global__ void k_degree(const void* __restrict__ ei, int E) {
    int i = blockIdx.x * blockDim.x + threadIdx.x;
    if (i >= E) return;
    int dst = edge_at(ei, (long long)E + i);
    atomicAdd(&g_deg[dst], 1);
}

__global__ void __launch_bounds__(SCAN_B) k_partial() {
    __shared__ int s_w[32];
    const int i = blockIdx.x * SCAN_B + threadIdx.x;
    int v = (i < N_NODES) ? g_deg[i] : 0;
#pragma unroll
    for (int off = 16; off > 0; off >>= 1)
        v += __shfl_xor_sync(FULL, v, off);
    if ((threadIdx.x & 31) == 0) s_w[threadIdx.x >> 5] = v;
    __syncthreads();
    if (threadIdx.x < 32) {
        int t = s_w[threadIdx.x];
#pragma unroll
        for (int off = 16; off > 0; off >>= 1)
            t += __shfl_xor_sync(FULL, t, off);
        if (threadIdx.x == 0) g_blocksum[blockIdx.x] = t;
    }
}

__global__ void k_scan_blocks() {
    __shared__ int s[NSCANB];
    if (threadIdx.x < NSCANB) s[threadIdx.x] = g_blocksum[threadIdx.x];
    __syncthreads();
    if (threadIdx.x == 0) {
        int run = 0;
        for (int b = 0; b < NSCANB; b++) { int t = s[b]; s[b] = run; run += t; }
    }
    __syncthreads();
    if (threadIdx.x < NSCANB) g_blockoff[threadIdx.x] = s[threadIdx.x];
}

__global__ void __launch_bounds__(SCAN_B) k_write() {
    __shared__ int s[SCAN_B];
    const int t = threadIdx.x;
    const int i = blockIdx.x * SCAN_B + t;
    const int d = (i < N_NODES) ? g_deg[i] : 0;
    s[t] = d;
    __syncthreads();
#pragma unroll
    for (int off = 1; off < SCAN_B; off <<= 1) {
        int v = (t >= off) ? s[t - off] : 0;
        __syncthreads();
        s[t] += v;
        __syncthreads();
    }
    if (i < N_NODES) {
        const int r = g_blockoff[blockIdx.x] + s[t] - d;  // exclusive
        g_rowptr[i] = r;
        g_cursor[i] = r;
    }
}

__global__ void k_fill(const void* __restrict__ ei, int E) {
    int i = blockIdx.x * blockDim.x + threadIdx.x;
    if (i >= E) return;
    int src = edge_at(ei, i);
    int dst = edge_at(ei, (long long)E + i);
    int pos = atomicAdd(&g_cursor[dst], 1);
    g_adj[pos] = src;
}

// ---------------- fused layer: gather-mean + linear + L2 norm (+ReLU) ----
// Gather: float4 per lane; one LDG.128 covers 2 neighbor rows (lanes 0-15 =
// neighbor A, 16-31 = neighbor B), halves combined via shfl_xor(16).
// GEMM: one warp owns 4 nodes; lane owns output features {lane, lane+32}.
template <int FOUT, bool RELU>
__global__ void __launch_bounds__(192)
k_layer(const float* __restrict__ xin,   // [N, 64]
        const float* __restrict__ Wl,    // [64, FOUT]
        const float* __restrict__ Wr,    // [64, FOUT]
        const float* __restrict__ bias,  // [FOUT]
        float* __restrict__ out)         // [N, FOUT]
{
    constexpr int OPT = FOUT / 32;  // outputs per thread (2 or 1)
    __shared__ float s_W[128 * FOUT];
    __shared__ __align__(16) float s_in[6][512];

    const int tid  = threadIdx.x;
    const int lane = tid & 31;
    const int w    = tid >> 5;
    const int fl4  = lane & 15;    // float4 slot within a 64-float row
    const int half = lane >> 4;    // 0: even neighbor, 1: odd neighbor

    for (int i = tid; i < 64 * FOUT; i += 192) {
        s_W[i]             = Wl[i];
        s_W[64 * FOUT + i] = Wr[i];
    }
    __syncthreads();

    float rb[OPT];
#pragma unroll
    for (int o = 0; o < OPT; o++) rb[o] = bias[lane + 32 * o];

    const int warpGid   = blockIdx.x * 6 + w;
    const int warpTotal = gridDim.x * 6;
    float* si = s_in[w];
    const float* xfl = xin + 4 * fl4;

    for (int base = warpGid * 4; base < N_NODES; base += warpTotal * 4) {
        // ---- phase 1: gather-mean for 4 nodes into shared ----
#pragma unroll
        for (int n = 0; n < 4; n++) {
            const int node  = base + n;
            const int deg   = g_deg[node];
            const int start = g_rowptr[node];
            const float inv = 1.0f / (float)max(deg, 1);
            float4 m = make_float4(0.f, 0.f, 0.f, 0.f);
            for (int j0 = 0; j0 < deg; j0 += 32) {
                const int rem = deg - j0;
                int src = 0;
                if (lane < rem) src = g_adj[start + j0 + lane];
                const int cnt   = min(32, rem);
                const int pairs = (cnt + 1) >> 1;
#pragma unroll 4
                for (int p = 0; p < pairs; p++) {
                    const int nb  = 2 * p + half;
                    const int idx = __shfl_sync(FULL, src, nb & 31);
                    if (nb < cnt) {
                        const float4 v = *(const float4*)(xfl + (long long)idx * 64);
                        m.x += v.x; m.y += v.y; m.z += v.z; m.w += v.w;
                    }
                }
            }
            m.x += __shfl_xor_sync(FULL, m.x, 16);
            m.y += __shfl_xor_sync(FULL, m.y, 16);
            m.z += __shfl_xor_sync(FULL, m.z, 16);
            m.w += __shfl_xor_sync(FULL, m.w, 16);
            if (half == 0) {
                m.x *= inv; m.y *= inv; m.z *= inv; m.w *= inv;
                *(float4*)(si + n * 128 + 4 * fl4) = m;
                const float4 xv = *(const float4*)(xin + node * 64 + 4 * fl4);
                *(float4*)(si + n * 128 + 64 + 4 * fl4) = xv;
            }
        }
        __syncwarp();

        // ---- phase 2: [mean|x] @ [Wl;Wr] with 4-node weight reuse ----
        float acc[4][OPT];
#pragma unroll
        for (int n = 0; n < 4; n++)
#pragma unroll
            for (int o = 0; o < OPT; o++) acc[n][o] = rb[o];

        const float4* si4 = (const float4*)si;
#pragma unroll 4
        for (int k4 = 0; k4 < 32; k4++) {
            float4 a0 = si4[k4];
            float4 a1 = si4[32 + k4];
            float4 a2 = si4[64 + k4];
            float4 a3 = si4[96 + k4];
#pragma unroll
            for (int kk = 0; kk < 4; kk++) {
                const int k = k4 * 4 + kk;
#pragma unroll
                for (int o = 0; o < OPT; o++) {
                    const float wv = s_W[k * FOUT + lane + 32 * o];
                    acc[0][o] += ((const float*)&a0)[kk] * wv;
                    acc[1][o] += ((const float*)&a1)[kk] * wv;
                    acc[2][o] += ((const float*)&a2)[kk] * wv;
                    acc[3][o] += ((const float*)&a3)[kk] * wv;
                }
            }
        }
        __syncwarp();

        // ---- phase 3: row L2-normalize (+ReLU) and store ----
#pragma unroll
        for (int n = 0; n < 4; n++) {
            float ss = 0.f;
#pragma unroll
            for (int o = 0; o < OPT; o++) ss += acc[n][o] * acc[n][o];
#pragma unroll
            for (int off = 16; off > 0; off >>= 1)
                ss += __shfl_xor_sync(FULL, ss, off);
            const float scale = 1.0f / fmaxf(sqrtf(ss), 1e-12f);
#pragma unroll
            for (int o = 0; o < OPT; o++) {
                float v = acc[n][o] * scale;
                if (RELU) v = fmaxf(v, 0.f);
                out[(base + n) * FOUT + lane + 32 * o] = v;
            }
        }
        __syncwarp();
    }
}

// ---------------- launch ----------------
extern "C" void kernel_launch(void* const* d_in, const int* in_sizes, int n_in,
                              void* d_out, int out_size) {
    (void)n_in; (void)out_size;
    const float* x   = (const float*)d_in[0];
    const void*  ei  = d_in[1];
    const float* W1l = (const float*)d_in[2];
    const float* b1  = (const float*)d_in[3];
    const float* W1r = (const float*)d_in[4];
    const float* W2l = (const float*)d_in[5];
    const float* b2  = (const float*)d_in[6];
    const float* W2r = (const float*)d_in[7];
    float* out = (float*)d_out;
    const int E = in_sizes[1] / 2;

    float* hptr = nullptr;
    cudaGetSymbolAddress((void**)&hptr, g_h);

    k_zerodetect<<<(N_NODES + 255) / 256, 256>>>((const unsigned int*)ei);
    k_degree<<<(E + 255) / 256, 256>>>(ei, E);
    k_partial<<<NSCANB, SCAN_B>>>();
    k_scan_blocks<<<1, 128>>>();
    k_write<<<NSCANB, SCAN_B>>>();
    k_fill<<<(E + 255) / 256, 256>>>(ei, E);

    k_layer<64, true ><<<740, 192>>>(x,    W1l, W1r, b1, hptr);
    k_layer<32, false><<<740, 192>>>(hptr, W2l, W2r, b2, out);
}